// round 6
// baseline (speedup 1.0000x reference)
#include <cuda_runtime.h>

#define NMAX 50176
#define FEAT 32
#define HID  64

// ---------------- scratch (device globals; no allocation allowed) ----------
__device__ __align__(16) float g_do_inv[NMAX];
__device__ __align__(16) float g_di_inv[NMAX];
__device__ __align__(16) float g_degc[NMAX];
__device__ __align__(16) float g_dis[NMAX];
__device__ __align__(16) float g_P1o[NMAX * FEAT];
__device__ __align__(16) float g_P1i[NMAX * FEAT];
__device__ __align__(16) float g_P2o[NMAX * FEAT];
__device__ __align__(16) float g_P2i[NMAX * FEAT];
__device__ __align__(16) float g_H[NMAX * HID];
__device__ __align__(16) float g_xw[NMAX * HID];
__device__ __align__(16) float g_y[NMAX * HID];
__device__ __align__(16) float g_Wcat[160 * 128];  // [k(160)][j(128)]: j<64 -> Z gate, j>=64 -> H gate
__device__ __align__(16) float g_bcat[128];
__device__ float g_S[HID];
__device__ float g_SS[HID];
__device__ float g_coef[HID];
__device__ float g_cnst;

__device__ __forceinline__ float sigm(float z) {
    return 1.0f / (1.0f + expf(-z));
}

// ---------------- kernels ----------------

// zero atomic targets + stats
__global__ void k_zero(int n) {
    int i = blockIdx.x * blockDim.x + threadIdx.x;
    int stride = gridDim.x * blockDim.x;
    for (int t = i; t < n; t += stride) {
        g_do_inv[t] = 0.f; g_di_inv[t] = 0.f; g_degc[t] = 0.f;
    }
    int nf = n * FEAT;
    for (int t = i; t < nf; t += stride) {
        g_P1o[t] = 0.f; g_P1i[t] = 0.f; g_P2o[t] = 0.f; g_P2i[t] = 0.f;
    }
    if (i < HID) { g_S[i] = 0.f; g_SS[i] = 0.f; }
}

// build fused 160x128 gate weight: blocks b of 32 k-rows:
// b0: Wg[0,0,:32]+Wg[1,0,:32], b1: Wg[0,1], b2: Wg[0,2], b3: Wg[1,1], b4: Wg[1,2]
__global__ void k_wcat(const float* __restrict__ Wz, const float* __restrict__ Wh,
                       const float* __restrict__ bz, const float* __restrict__ bh) {
    int idx = blockIdx.x * blockDim.x + threadIdx.x;
    if (idx < 160 * 128) {
        int k5 = idx >> 7;          // 0..159
        int j  = idx & 127;         // 0..127
        int b = k5 >> 5;            // block
        int f = k5 & 31;            // feature row (first 32 of fin=96)
        const float* Wg = (j < 64) ? Wz : Wh;
        int jj = j & 63;
        float v;
        if (b == 0) {
            v = Wg[((0 * 3 + 0) * 96 + f) * 64 + jj] + Wg[((1 * 3 + 0) * 96 + f) * 64 + jj];
        } else {
            int d = (b <= 2) ? 0 : 1;
            int k = (b <= 2) ? b : (b - 2);
            v = Wg[((d * 3 + k) * 96 + f) * 64 + jj];
        }
        g_Wcat[idx] = v;
    } else if (idx < 160 * 128 + 128) {
        int j = idx - 160 * 128;
        g_bcat[j] = (j < 64) ? bz[j] : bh[j - 64];
    }
}

// weighted degrees + unweighted in-degree (GCN)
__global__ void k_deg(const int* __restrict__ row, const int* __restrict__ col,
                      const float* __restrict__ ew, int E) {
    int e = blockIdx.x * blockDim.x + threadIdx.x;
    if (e >= E) return;
    float w = ew[e];
    atomicAdd(&g_do_inv[row[e]], w);
    atomicAdd(&g_di_inv[col[e]], w);
    atomicAdd(&g_degc[col[e]], 1.0f);
}

__global__ void k_inv(int n) {
    int i = blockIdx.x * blockDim.x + threadIdx.x;
    if (i >= n) return;
    float a = g_do_inv[i];
    g_do_inv[i] = (a > 0.f) ? (1.0f / a) : 0.f;
    float b = g_di_inv[i];
    g_di_inv[i] = (b > 0.f) ? (1.0f / b) : 0.f;
    g_dis[i] = rsqrtf(g_degc[i] + 1.0f);
}

// one diffusion hop, both directions. warp per edge, lane per feature.
// hop==1: x -> P1o/P1i.  hop==2: P1o -> P2o, P1i -> P2i.
// NOTE: src/dst resolved INSIDE device code — passing __device__ globals as
// host-side kernel args yields the host shadow symbol (silently "works" on
// GB300 via ATS but targets host memory). That was the R3/R4 bug.
__global__ void k_spmm32(const float* __restrict__ x, int hop,
                         const int* __restrict__ row, const int* __restrict__ col,
                         const float* __restrict__ ew, int E) {
    int t = blockIdx.x * blockDim.x + threadIdx.x;
    int e = t >> 5;
    int lane = t & 31;
    if (e >= E) return;
    const float* srcO = (hop == 1) ? x : g_P1o;
    const float* srcI = (hop == 1) ? x : g_P1i;
    float* dstO = (hop == 1) ? g_P1o : g_P2o;
    float* dstI = (hop == 1) ? g_P1i : g_P2i;
    int r = row[e];
    int c = col[e];
    float w = ew[e];
    float wo = w * g_do_inv[r];
    float wi = w * g_di_inv[c];
    float vO = srcO[r * FEAT + lane];
    float vI = srcI[c * FEAT + lane];
    atomicAdd(&dstO[c * FEAT + lane], wo * vO);
    atomicAdd(&dstI[r * FEAT + lane], wi * vI);
}

// fused gate GEMM: [x|P1o|P2o|P1i|P2i](Nx160) @ Wcat(160x128) + bcat,
// then H = (1 - sigmoid(Zd)) * tanh(Hd).
// Lane j owns hidden units 2j, 2j+1: accumulates Z cols (2j,2j+1) and
// H cols (64+2j, 64+2j+1). No cross-lane exchange needed.
__global__ void __launch_bounds__(128) k_gates(const float* __restrict__ x, int n) {
    __shared__ float ps[32][160];  // activation tile (20 KB)
    int tid = threadIdx.x;
    int n0 = blockIdx.x * 32;

    for (int idx = tid; idx < 32 * 160; idx += 128) {
        int m = idx / 160;
        int k = idx - m * 160;
        int node = n0 + m;
        float v = 0.f;
        if (node < n) {
            int b = k >> 5, f = k & 31;
            const float* src = (b == 0) ? x : (b == 1) ? g_P1o : (b == 2) ? g_P2o
                             : (b == 3) ? g_P1i : g_P2i;
            v = src[node * FEAT + f];
        }
        ps[m][k] = v;
    }
    __syncthreads();

    int w = tid >> 5, j = tid & 31;
    int m0 = w * 8;

    float az0[8], az1[8], ah0[8], ah1[8];
    float bz0 = g_bcat[2 * j],      bz1 = g_bcat[2 * j + 1];
    float bh0 = g_bcat[64 + 2 * j], bh1 = g_bcat[64 + 2 * j + 1];
#pragma unroll
    for (int m = 0; m < 8; m++) { az0[m] = bz0; az1[m] = bz1; ah0[m] = bh0; ah1[m] = bh1; }

    for (int k = 0; k < 160; k++) {
        float2 wz = *reinterpret_cast<const float2*>(&g_Wcat[k * 128 + 2 * j]);
        float2 wh = *reinterpret_cast<const float2*>(&g_Wcat[k * 128 + 64 + 2 * j]);
#pragma unroll
        for (int m = 0; m < 8; m++) {
            float p = ps[m0 + m][k];
            az0[m] = fmaf(wz.x, p, az0[m]);
            az1[m] = fmaf(wz.y, p, az1[m]);
            ah0[m] = fmaf(wh.x, p, ah0[m]);
            ah1[m] = fmaf(wh.y, p, ah1[m]);
        }
    }

#pragma unroll
    for (int m = 0; m < 8; m++) {
        int node = n0 + m0 + m;
        if (node < n) {
            float2 h;
            h.x = (1.f - sigm(az0[m])) * tanhf(ah0[m]);
            h.y = (1.f - sigm(az1[m])) * tanhf(ah1[m]);
            *reinterpret_cast<float2*>(&g_H[node * HID + 2 * j]) = h;
        }
    }
}

// xw = H @ gcn_w ; y = dis^2 * xw + gcn_b  (initializes y before GCN atomics)
__global__ void __launch_bounds__(128) k_xw(const float* __restrict__ gcn_w,
                                            const float* __restrict__ gcn_b, int n) {
    __shared__ float hs[32][64];  // 8 KB
    int tid = threadIdx.x;
    int n0 = blockIdx.x * 32;

    for (int idx = tid; idx < 32 * 64; idx += 128) {
        int m = idx >> 6, k = idx & 63;
        int node = n0 + m;
        hs[m][k] = (node < n) ? g_H[node * HID + k] : 0.f;
    }
    __syncthreads();

    int w = tid >> 5, j = tid & 31;
    int m0 = w * 8;

    float a0[8], a1[8];
#pragma unroll
    for (int m = 0; m < 8; m++) { a0[m] = 0.f; a1[m] = 0.f; }

    for (int k = 0; k < 64; k++) {
        float2 wv = *reinterpret_cast<const float2*>(&gcn_w[k * 64 + 2 * j]);  // cols 2j,2j+1
#pragma unroll
        for (int m = 0; m < 8; m++) {
            float p = hs[m0 + m][k];
            a0[m] = fmaf(wv.x, p, a0[m]);
            a1[m] = fmaf(wv.y, p, a1[m]);
        }
    }

    float2 gb = *reinterpret_cast<const float2*>(&gcn_b[2 * j]);
#pragma unroll
    for (int m = 0; m < 8; m++) {
        int node = n0 + m0 + m;
        if (node < n) {
            float2 a; a.x = a0[m]; a.y = a1[m];
            *reinterpret_cast<float2*>(&g_xw[node * HID + 2 * j]) = a;
            float d = g_dis[node];
            float d2 = d * d;
            float2 yv;
            yv.x = fmaf(d2, a.x, gb.x);
            yv.y = fmaf(d2, a.y, gb.y);
            *reinterpret_cast<float2*>(&g_y[node * HID + 2 * j]) = yv;
        }
    }
}

// GCN message passing: y[c] += dis[r]*dis[c] * xw[r]   (warp per edge, 2 feats/lane)
__global__ void k_gcn(const int* __restrict__ row, const int* __restrict__ col, int E) {
    int t = blockIdx.x * blockDim.x + threadIdx.x;
    int e = t >> 5;
    int lane = t & 31;
    if (e >= E) return;
    int r = row[e];
    int c = col[e];
    float nrm = g_dis[r] * g_dis[c];
    atomicAdd(&g_y[c * HID + lane],      nrm * g_xw[r * HID + lane]);
    atomicAdd(&g_y[c * HID + lane + 32], nrm * g_xw[r * HID + lane + 32]);
}

// per-channel sums of relu(y) and relu(y)^2
__global__ void k_stats(int n) {
    int tid = threadIdx.x;
    int c = tid & 63;
    int rg = tid >> 6;  // 0..3
    float s = 0.f, ss = 0.f;
    for (int r = blockIdx.x * 4 + rg; r < n; r += gridDim.x * 4) {
        float v = g_y[r * HID + c];
        v = fmaxf(v, 0.f);
        s += v;
        ss += v * v;
    }
    __shared__ float sm1[256], sm2[256];
    sm1[tid] = s; sm2[tid] = ss;
    __syncthreads();
    if (tid < 64) {
        s  = sm1[tid] + sm1[tid + 64] + sm1[tid + 128] + sm1[tid + 192];
        ss = sm2[tid] + sm2[tid + 64] + sm2[tid + 128] + sm2[tid + 192];
        atomicAdd(&g_S[c], s);
        atomicAdd(&g_SS[c], ss);
    }
}

// fold BN + linear: coef[c] = gamma*rsqrt(var+eps)*lin_w[c];
// cnst = sum_c (beta - mean*a)*lin_w[c] + lin_b
__global__ void k_coef(const float* __restrict__ gamma, const float* __restrict__ beta,
                       const float* __restrict__ lw, const float* __restrict__ lb, int n) {
    int c = threadIdx.x;
    float invn = 1.0f / (float)n;
    float mean = g_S[c] * invn;
    float var = g_SS[c] * invn - mean * mean;
    float a = gamma[c] * rsqrtf(var + 1e-5f);
    g_coef[c] = a * lw[c];
    float part = (beta[c] - mean * a) * lw[c];
    __shared__ float sm[64];
    sm[c] = part;
    __syncthreads();
    if (c == 0) {
        float t = lb[0];
        for (int i = 0; i < 64; i++) t += sm[i];
        g_cnst = t;
    }
}

// out[n] = dot(relu(y[n,:]), coef) + cnst   (warp per node)
__global__ void k_out(float* __restrict__ out, int n) {
    int t = blockIdx.x * blockDim.x + threadIdx.x;
    int node = t >> 5;
    int j = t & 31;
    if (node >= n) return;
    float v1 = fmaxf(g_y[node * HID + j], 0.f) * g_coef[j];
    float v2 = fmaxf(g_y[node * HID + j + 32], 0.f) * g_coef[j + 32];
    float acc = v1 + v2;
#pragma unroll
    for (int o = 16; o > 0; o >>= 1) acc += __shfl_down_sync(0xffffffffu, acc, o);
    if (j == 0) out[node] = acc + g_cnst;
}

// ---------------- launch ----------------
extern "C" void kernel_launch(void* const* d_in, const int* in_sizes, int n_in,
                              void* d_out, int out_size) {
    const float* x     = (const float*)d_in[0];
    const int*   ei    = (const int*)d_in[1];
    const float* ew    = (const float*)d_in[2];
    const float* Wz    = (const float*)d_in[3];
    const float* bz    = (const float*)d_in[4];
    const float* Wh    = (const float*)d_in[7];
    const float* bh    = (const float*)d_in[8];
    const float* gcn_w = (const float*)d_in[9];
    const float* gcn_b = (const float*)d_in[10];
    const float* gamma = (const float*)d_in[11];
    const float* beta  = (const float*)d_in[12];
    const float* lw    = (const float*)d_in[13];
    const float* lb    = (const float*)d_in[14];
    float* out = (float*)d_out;

    int n = in_sizes[0] / FEAT;
    int E = in_sizes[2];
    const int* row = ei;
    const int* col = ei + E;

    int edge_warps_grid = (E * 32 + 255) / 256;

    k_zero<<<2048, 256>>>(n);
    k_wcat<<<(160 * 128 + 128 + 255) / 256, 256>>>(Wz, Wh, bz, bh);
    k_deg<<<(E + 255) / 256, 256>>>(row, col, ew, E);
    k_inv<<<(n + 255) / 256, 256>>>(n);
    // hop 1: X -> P1o, P1i   (dst/src resolved device-side)
    k_spmm32<<<edge_warps_grid, 256>>>(x, 1, row, col, ew, E);
    // hop 2: P1o -> P2o, P1i -> P2i
    k_spmm32<<<edge_warps_grid, 256>>>(x, 2, row, col, ew, E);
    // fused gates -> H
    k_gates<<<(n + 31) / 32, 128>>>(x, n);
    // GCN dense + self term
    k_xw<<<(n + 31) / 32, 128>>>(gcn_w, gcn_b, n);
    // GCN message passing
    k_gcn<<<edge_warps_grid, 256>>>(row, col, E);
    // BN stats
    k_stats<<<512, 256>>>(n);
    k_coef<<<1, 64>>>(gamma, beta, lw, lb, n);
    // final output
    k_out<<<(n * 32 + 255) / 256, 256>>>(out, n);
}

// round 7
// speedup vs baseline: 1.3230x; 1.3230x over previous
#include <cuda_runtime.h>

#define NMAX 50176
#define FEAT 32
#define HID  64

typedef unsigned long long ull;

// ---------------- scratch (device globals; no allocation allowed) ----------
__device__ __align__(16) float g_do_inv[NMAX];
__device__ __align__(16) float g_di_inv[NMAX];
__device__ __align__(16) float g_degc[NMAX];
__device__ __align__(16) float g_dis[NMAX];
__device__ __align__(16) float g_P1o[NMAX * FEAT];
__device__ __align__(16) float g_P1i[NMAX * FEAT];
__device__ __align__(16) float g_P2o[NMAX * FEAT];
__device__ __align__(16) float g_P2i[NMAX * FEAT];
__device__ __align__(16) float g_H[NMAX * HID];
__device__ __align__(16) float g_xw[NMAX * HID];
__device__ __align__(16) float g_y[NMAX * HID];
__device__ __align__(16) float g_Wcat[160 * 128];  // [k(160)][j(128)]: j<64 -> Z, j>=64 -> Htilde
__device__ __align__(16) float g_bcat[128];
__device__ float g_S[HID];
__device__ float g_SS[HID];
__device__ float g_coef[HID];
__device__ float g_cnst;

// ---------------- helpers ----------------
__device__ __forceinline__ float sigm(float z) { return 1.0f / (1.0f + expf(-z)); }

__device__ __forceinline__ void red4(float* p, float a, float b, float c, float d) {
    asm volatile("red.global.add.v4.f32 [%0], {%1, %2, %3, %4};"
                 :: "l"(p), "f"(a), "f"(b), "f"(c), "f"(d) : "memory");
}

__device__ __forceinline__ ull pk(float lo, float hi) {
    ull r; asm("mov.b64 %0, {%1, %2};" : "=l"(r) : "f"(lo), "f"(hi)); return r;
}
__device__ __forceinline__ float2 upk(ull v) {
    float2 r; asm("mov.b64 {%0, %1}, %2;" : "=f"(r.x), "=f"(r.y) : "l"(v)); return r;
}
__device__ __forceinline__ void fma2(ull& d, ull a, ull b) {
    asm("fma.rn.f32x2 %0, %1, %2, %0;" : "+l"(d) : "l"(a), "l"(b));
}

// ---------------- kernels ----------------

// zero atomic targets + stats
__global__ void k_zero(int n) {
    int i = blockIdx.x * blockDim.x + threadIdx.x;
    int stride = gridDim.x * blockDim.x;
    for (int t = i; t < n; t += stride) {
        g_do_inv[t] = 0.f; g_di_inv[t] = 0.f; g_degc[t] = 0.f;
    }
    int nf = n * FEAT;
    for (int t = i; t < nf; t += stride) {
        g_P1o[t] = 0.f; g_P1i[t] = 0.f; g_P2o[t] = 0.f; g_P2i[t] = 0.f;
    }
    if (i < HID) { g_S[i] = 0.f; g_SS[i] = 0.f; }
}

// build fused 160x128 gate weight
__global__ void k_wcat(const float* __restrict__ Wz, const float* __restrict__ Wh,
                       const float* __restrict__ bz, const float* __restrict__ bh) {
    int idx = blockIdx.x * blockDim.x + threadIdx.x;
    if (idx < 160 * 128) {
        int k5 = idx >> 7;
        int j  = idx & 127;
        int b = k5 >> 5;
        int f = k5 & 31;
        const float* Wg = (j < 64) ? Wz : Wh;
        int jj = j & 63;
        float v;
        if (b == 0) {
            v = Wg[((0 * 3 + 0) * 96 + f) * 64 + jj] + Wg[((1 * 3 + 0) * 96 + f) * 64 + jj];
        } else {
            int d = (b <= 2) ? 0 : 1;
            int k = (b <= 2) ? b : (b - 2);
            v = Wg[((d * 3 + k) * 96 + f) * 64 + jj];
        }
        g_Wcat[idx] = v;
    } else if (idx < 160 * 128 + 128) {
        int j = idx - 160 * 128;
        g_bcat[j] = (j < 64) ? bz[j] : bh[j - 64];
    }
}

// weighted degrees + unweighted in-degree (GCN)
__global__ void k_deg(const int* __restrict__ row, const int* __restrict__ col,
                      const float* __restrict__ ew, int E) {
    int e = blockIdx.x * blockDim.x + threadIdx.x;
    if (e >= E) return;
    float w = ew[e];
    atomicAdd(&g_do_inv[row[e]], w);
    atomicAdd(&g_di_inv[col[e]], w);
    atomicAdd(&g_degc[col[e]], 1.0f);
}

__global__ void k_inv(int n) {
    int i = blockIdx.x * blockDim.x + threadIdx.x;
    if (i >= n) return;
    float a = g_do_inv[i];
    g_do_inv[i] = (a > 0.f) ? (1.0f / a) : 0.f;
    float b = g_di_inv[i];
    g_di_inv[i] = (b > 0.f) ? (1.0f / b) : 0.f;
    g_dis[i] = rsqrtf(g_degc[i] + 1.0f);
}

// one diffusion hop, both directions. 8 threads per edge, float4 per thread,
// vectorized red.global.add.v4.f32 (4x fewer RED messages than scalar atomics).
// hop==1: x -> P1o/P1i.  hop==2: P1o -> P2o, P1i -> P2i.
// (src/dst resolved device-side; host-side &__device__ global was the R3/R4 bug)
__global__ void k_spmm(const float* __restrict__ x, int hop,
                       const int* __restrict__ row, const int* __restrict__ col,
                       const float* __restrict__ ew, int E) {
    int t = blockIdx.x * blockDim.x + threadIdx.x;
    int e = t >> 3;
    int q = (t & 7) * 4;
    if (e >= E) return;
    const float* srcO = (hop == 1) ? x : g_P1o;
    const float* srcI = (hop == 1) ? x : g_P1i;
    float* dstO = (hop == 1) ? g_P1o : g_P2o;
    float* dstI = (hop == 1) ? g_P1i : g_P2i;
    int r = row[e];
    int c = col[e];
    float w = ew[e];
    float wo = w * g_do_inv[r];
    float wi = w * g_di_inv[c];
    float4 vO = *reinterpret_cast<const float4*>(&srcO[r * FEAT + q]);
    float4 vI = *reinterpret_cast<const float4*>(&srcI[c * FEAT + q]);
    red4(&dstO[c * FEAT + q], wo * vO.x, wo * vO.y, wo * vO.z, wo * vO.w);
    red4(&dstI[r * FEAT + q], wi * vI.x, wi * vI.y, wi * vI.z, wi * vI.w);
}

// fused gate GEMM (f32x2 packed): [x|P1o|P2o|P1i|P2i](Nx160) @ Wcat(160x128)+bcat,
// then H = (1-sigmoid(Zd))*tanh(Hd). Lane j<16 owns Z channels 4j..4j+3,
// lane j+16 owns Hd for the same channels; combine via shfl_xor(16).
// (This exact kernel was functionally cross-validated against the scalar
// version in R3/R4: identical outputs.)
__global__ void __launch_bounds__(128) k_gates(const float* __restrict__ x, int n) {
    __shared__ ull p2s[32 * 160];  // activation duplicated into both f32x2 halves (40 KB)
    int tid = threadIdx.x;
    int n0 = blockIdx.x * 32;

    for (int idx = tid; idx < 32 * 160; idx += 128) {
        int m = idx / 160;
        int k = idx - m * 160;
        int node = n0 + m;
        float v = 0.f;
        if (node < n) {
            int b = k >> 5, f = k & 31;
            const float* src = (b == 0) ? x : (b == 1) ? g_P1o : (b == 2) ? g_P2o
                             : (b == 3) ? g_P1i : g_P2i;
            v = src[node * FEAT + f];
        }
        p2s[idx] = pk(v, v);
    }
    __syncthreads();

    int w = tid >> 5, j = tid & 31;
    int m0 = w * 8;

    ull acc[8][2];
    float4 bv = *reinterpret_cast<const float4*>(&g_bcat[4 * j]);
    ull b01 = pk(bv.x, bv.y), b23 = pk(bv.z, bv.w);
#pragma unroll
    for (int m = 0; m < 8; m++) { acc[m][0] = b01; acc[m][1] = b23; }

    const ulonglong2* Wm = reinterpret_cast<const ulonglong2*>(g_Wcat);
    for (int k = 0; k < 160; k++) {
        ulonglong2 wv = Wm[k * 32 + j];  // cols 4j..4j+3 of row k
#pragma unroll
        for (int m = 0; m < 8; m++) {
            ull pv = p2s[(m0 + m) * 160 + k];
            fma2(acc[m][0], wv.x, pv);
            fma2(acc[m][1], wv.y, pv);
        }
    }

#pragma unroll
    for (int m = 0; m < 8; m++) {
        int node = n0 + m0 + m;
        float2 a0 = upk(acc[m][0]);
        float2 a1 = upk(acc[m][1]);
        float p0 = __shfl_xor_sync(0xffffffffu, a0.x, 16);
        float p1 = __shfl_xor_sync(0xffffffffu, a0.y, 16);
        float p2 = __shfl_xor_sync(0xffffffffu, a1.x, 16);
        float p3 = __shfl_xor_sync(0xffffffffu, a1.y, 16);
        if (j < 16 && node < n) {
            float4 h;
            h.x = (1.f - sigm(a0.x)) * tanhf(p0);
            h.y = (1.f - sigm(a0.y)) * tanhf(p1);
            h.z = (1.f - sigm(a1.x)) * tanhf(p2);
            h.w = (1.f - sigm(a1.y)) * tanhf(p3);
            *reinterpret_cast<float4*>(&g_H[node * HID + 4 * j]) = h;
        }
    }
}

// xw = H @ gcn_w ; y = dis^2 * xw + gcn_b  (f32x2; cross-validated in R3/R4)
__global__ void __launch_bounds__(128) k_xw(const float* __restrict__ gcn_w,
                                            const float* __restrict__ gcn_b, int n) {
    __shared__ ull h2s[32 * 64];  // 16 KB
    int tid = threadIdx.x;
    int n0 = blockIdx.x * 32;

    for (int idx = tid; idx < 32 * 64; idx += 128) {
        int m = idx >> 6, k = idx & 63;
        int node = n0 + m;
        float v = (node < n) ? g_H[node * HID + k] : 0.f;
        h2s[idx] = pk(v, v);
    }
    __syncthreads();

    int w = tid >> 5, j = tid & 31;
    int m0 = w * 8;

    ull acc[8];
#pragma unroll
    for (int m = 0; m < 8; m++) acc[m] = 0ull;

    for (int k = 0; k < 64; k++) {
        ull wv = *reinterpret_cast<const ull*>(&gcn_w[k * 64 + 2 * j]);  // cols 2j,2j+1
#pragma unroll
        for (int m = 0; m < 8; m++) {
            fma2(acc[m], wv, h2s[(m0 + m) * 64 + k]);
        }
    }

    float2 gb = *reinterpret_cast<const float2*>(&gcn_b[2 * j]);
#pragma unroll
    for (int m = 0; m < 8; m++) {
        int node = n0 + m0 + m;
        if (node < n) {
            float2 a = upk(acc[m]);
            *reinterpret_cast<float2*>(&g_xw[node * HID + 2 * j]) = a;
            float d = g_dis[node];
            float d2 = d * d;
            float2 yv;
            yv.x = fmaf(d2, a.x, gb.x);
            yv.y = fmaf(d2, a.y, gb.y);
            *reinterpret_cast<float2*>(&g_y[node * HID + 2 * j]) = yv;
        }
    }
}

// GCN message passing: y[c] += dis[r]*dis[c] * xw[r]
// 16 threads per edge, float4 + red.v4 per thread.
__global__ void k_gcn(const int* __restrict__ row, const int* __restrict__ col, int E) {
    int t = blockIdx.x * blockDim.x + threadIdx.x;
    int e = t >> 4;
    int q = (t & 15) * 4;
    if (e >= E) return;
    int r = row[e];
    int c = col[e];
    float nrm = g_dis[r] * g_dis[c];
    float4 v = *reinterpret_cast<const float4*>(&g_xw[r * HID + q]);
    red4(&g_y[c * HID + q], nrm * v.x, nrm * v.y, nrm * v.z, nrm * v.w);
}

// per-channel sums of relu(y) and relu(y)^2
__global__ void k_stats(int n) {
    int tid = threadIdx.x;
    int c = tid & 63;
    int rg = tid >> 6;  // 0..3
    float s = 0.f, ss = 0.f;
    for (int r = blockIdx.x * 4 + rg; r < n; r += gridDim.x * 4) {
        float v = g_y[r * HID + c];
        v = fmaxf(v, 0.f);
        s += v;
        ss += v * v;
    }
    __shared__ float sm1[256], sm2[256];
    sm1[tid] = s; sm2[tid] = ss;
    __syncthreads();
    if (tid < 64) {
        s  = sm1[tid] + sm1[tid + 64] + sm1[tid + 128] + sm1[tid + 192];
        ss = sm2[tid] + sm2[tid + 64] + sm2[tid + 128] + sm2[tid + 192];
        atomicAdd(&g_S[c], s);
        atomicAdd(&g_SS[c], ss);
    }
}

// fold BN + linear
__global__ void k_coef(const float* __restrict__ gamma, const float* __restrict__ beta,
                       const float* __restrict__ lw, const float* __restrict__ lb, int n) {
    int c = threadIdx.x;
    float invn = 1.0f / (float)n;
    float mean = g_S[c] * invn;
    float var = g_SS[c] * invn - mean * mean;
    float a = gamma[c] * rsqrtf(var + 1e-5f);
    g_coef[c] = a * lw[c];
    float part = (beta[c] - mean * a) * lw[c];
    __shared__ float sm[64];
    sm[c] = part;
    __syncthreads();
    if (c == 0) {
        float t = lb[0];
        for (int i = 0; i < 64; i++) t += sm[i];
        g_cnst = t;
    }
}

// out[n] = dot(relu(y[n,:]), coef) + cnst   (warp per node)
__global__ void k_out(float* __restrict__ out, int n) {
    int t = blockIdx.x * blockDim.x + threadIdx.x;
    int node = t >> 5;
    int j = t & 31;
    if (node >= n) return;
    float v1 = fmaxf(g_y[node * HID + j], 0.f) * g_coef[j];
    float v2 = fmaxf(g_y[node * HID + j + 32], 0.f) * g_coef[j + 32];
    float acc = v1 + v2;
#pragma unroll
    for (int o = 16; o > 0; o >>= 1) acc += __shfl_down_sync(0xffffffffu, acc, o);
    if (j == 0) out[node] = acc + g_cnst;
}

// ---------------- launch ----------------
extern "C" void kernel_launch(void* const* d_in, const int* in_sizes, int n_in,
                              void* d_out, int out_size) {
    const float* x     = (const float*)d_in[0];
    const int*   ei    = (const int*)d_in[1];
    const float* ew    = (const float*)d_in[2];
    const float* Wz    = (const float*)d_in[3];
    const float* bz    = (const float*)d_in[4];
    const float* Wh    = (const float*)d_in[7];
    const float* bh    = (const float*)d_in[8];
    const float* gcn_w = (const float*)d_in[9];
    const float* gcn_b = (const float*)d_in[10];
    const float* gamma = (const float*)d_in[11];
    const float* beta  = (const float*)d_in[12];
    const float* lw    = (const float*)d_in[13];
    const float* lb    = (const float*)d_in[14];
    float* out = (float*)d_out;

    int n = in_sizes[0] / FEAT;
    int E = in_sizes[2];
    const int* row = ei;
    const int* col = ei + E;

    k_zero<<<2048, 256>>>(n);
    k_wcat<<<(160 * 128 + 128 + 255) / 256, 256>>>(Wz, Wh, bz, bh);
    k_deg<<<(E + 255) / 256, 256>>>(row, col, ew, E);
    k_inv<<<(n + 255) / 256, 256>>>(n);
    // hop 1: X -> P1o, P1i
    k_spmm<<<(E * 8 + 255) / 256, 256>>>(x, 1, row, col, ew, E);
    // hop 2: P1o -> P2o, P1i -> P2i
    k_spmm<<<(E * 8 + 255) / 256, 256>>>(x, 2, row, col, ew, E);
    // fused gates -> H
    k_gates<<<(n + 31) / 32, 128>>>(x, n);
    // GCN dense + self term
    k_xw<<<(n + 31) / 32, 128>>>(gcn_w, gcn_b, n);
    // GCN message passing
    k_gcn<<<(E * 16 + 255) / 256, 256>>>(row, col, E);
    // BN stats
    k_stats<<<512, 256>>>(n);
    k_coef<<<1, 64>>>(gamma, beta, lw, lb, n);
    // final output
    k_out<<<(n * 32 + 255) / 256, 256>>>(out, n);
}